// round 7
// baseline (speedup 1.0000x reference)
#include <cuda_runtime.h>
#include <cstdint>

// Problem constants: T tables, E rows/table, D dim, B batch, L bag length
constexpr int T = 4;
constexpr int E = 1000000;
constexpr int D = 128;
constexpr int B = 8192;
constexpr int L = 32;

// One warp per PAIR of bags (t, 2p) and (t, 2p+1). Lane l owns float4 chunk l
// of the D=128 row (32 lanes x 16B = 512B row, fully coalesced).
// Two independent accumulator chains per lane -> ~2x front-batchable LDGs.
// indices: int32 [T, B, L]; weights: fp32 [T, E, D]; out: fp32 [B, T*D]
__global__ void __launch_bounds__(256) embbag_kernel(
    const int* __restrict__ indices,
    const float* __restrict__ weights,
    float* __restrict__ out)
{
    const int warp_global = (blockIdx.x * blockDim.x + threadIdx.x) >> 5;
    const int lane = threadIdx.x & 31;
    constexpr int PAIRS_PER_TABLE = B / 2;
    if (warp_global >= T * PAIRS_PER_TABLE) return;

    const int t = warp_global / PAIRS_PER_TABLE;
    const int p = warp_global % PAIRS_PER_TABLE;
    const int b0 = 2 * p;
    const int b1 = 2 * p + 1;

    // Coalesced per-warp index loads: lane l reads index l of each bag (128B each).
    const int idx0 = indices[((size_t)t * B + b0) * L + lane];
    const int idx1 = indices[((size_t)t * B + b1) * L + lane];

    // Base of this table, as float4 chunks (32 per row).
    const float4* __restrict__ wbase =
        reinterpret_cast<const float4*>(weights) + (size_t)t * E * (D / 4);

    float4 acc0 = make_float4(0.f, 0.f, 0.f, 0.f);
    float4 acc1 = make_float4(0.f, 0.f, 0.f, 0.f);

#pragma unroll
    for (int j = 0; j < L; j++) {
        const int r0 = __shfl_sync(0xFFFFFFFFu, idx0, j);
        const int r1 = __shfl_sync(0xFFFFFFFFu, idx1, j);
        const float4 v0 = __ldg(wbase + (size_t)r0 * (D / 4) + lane);
        const float4 v1 = __ldg(wbase + (size_t)r1 * (D / 4) + lane);
        acc0.x += v0.x; acc0.y += v0.y; acc0.z += v0.z; acc0.w += v0.w;
        acc1.x += v1.x; acc1.y += v1.y; acc1.z += v1.z; acc1.w += v1.w;
    }

    // Streaming stores: output is write-once, never re-read -> keep it out of
    // L2 so weight rows stay resident (more duplicate-row hits).
    float4* __restrict__ o0 =
        reinterpret_cast<float4*>(out) + ((size_t)b0 * T + t) * (D / 4) + lane;
    float4* __restrict__ o1 =
        reinterpret_cast<float4*>(out) + ((size_t)b1 * T + t) * (D / 4) + lane;
    __stwt(o0, acc0);
    __stwt(o1, acc1);
}

extern "C" void kernel_launch(void* const* d_in, const int* in_sizes, int n_in,
                              void* d_out, int out_size)
{
    const int*   indices = (const int*)d_in[0];   // [T, B, L] int32
    const float* weights = (const float*)d_in[1]; // [T, E, D] fp32
    float*       out     = (float*)d_out;         // [B, T*D] fp32

    const int total_warps = T * (B / 2);          // 16384
    const int threads = 256;                      // 8 warps/block
    const int blocks = (total_warps * 32 + threads - 1) / threads; // 2048

    embbag_kernel<<<blocks, threads>>>(indices, weights, out);
}

// round 9
// speedup vs baseline: 1.0345x; 1.0345x over previous
#include <cuda_runtime.h>
#include <cstdint>

// Problem constants: T tables, E rows/table, D dim, B batch, L bag length
constexpr int T = 4;
constexpr int E = 1000000;
constexpr int D = 128;
constexpr int B = 8192;
constexpr int L = 32;

// One warp per (t, b) bag. Lane l owns float4 chunk l of the D=128 row
// (32 lanes x 16B = 512B row, fully coalesced).
// DRAM-bound at the random-512B-granule ceiling (~6.15 TB/s); all choices here
// aim to minimize DRAM bytes:
//   - indices loaded with __ldcs (single-use, don't pollute L2)
//   - output stored with __stwt (write-once, keep L2 for weight rows)
//   - weights on the default caching path (one table's unique working set
//     ~118MB nearly fits the 126MB L2 -> duplicate-row hits)
// indices: int32 [T, B, L]; weights: fp32 [T, E, D]; out: fp32 [B, T*D]
__global__ void __launch_bounds__(256) embbag_kernel(
    const int* __restrict__ indices,
    const float* __restrict__ weights,
    float* __restrict__ out)
{
    const int warp_global = (blockIdx.x * blockDim.x + threadIdx.x) >> 5;
    const int lane = threadIdx.x & 31;
    if (warp_global >= T * B) return;

    const int t = warp_global / B;
    const int b = warp_global % B;

    // Coalesced per-warp index load: lane l reads index l of this bag (128B).
    const int my_idx = __ldcs(indices + ((size_t)t * B + b) * L + lane);

    // Base of this table, as float4 chunks (32 per row).
    const float4* __restrict__ wbase =
        reinterpret_cast<const float4*>(weights) + (size_t)t * E * (D / 4);

    float4 acc = make_float4(0.f, 0.f, 0.f, 0.f);

#pragma unroll
    for (int j = 0; j < L; j++) {
        const int r = __shfl_sync(0xFFFFFFFFu, my_idx, j);
        const float4 v = __ldg(wbase + (size_t)r * (D / 4) + lane);
        acc.x += v.x;
        acc.y += v.y;
        acc.z += v.z;
        acc.w += v.w;
    }

    // Streaming store: out[b][t*D + lane*4 ..] as float4, bypassing L2 fill.
    float4* __restrict__ o =
        reinterpret_cast<float4*>(out) + ((size_t)b * T + t) * (D / 4) + lane;
    __stwt(o, acc);
}

extern "C" void kernel_launch(void* const* d_in, const int* in_sizes, int n_in,
                              void* d_out, int out_size)
{
    const int*   indices = (const int*)d_in[0];   // [T, B, L] int32
    const float* weights = (const float*)d_in[1]; // [T, E, D] fp32
    float*       out     = (float*)d_out;         // [B, T*D] fp32

    const int total_warps = T * B;            // 32768
    const int threads = 256;                  // 8 warps/block
    const int blocks = (total_warps * 32 + threads - 1) / threads; // 4096

    embbag_kernel<<<blocks, threads>>>(indices, weights, out);
}